// round 4
// baseline (speedup 1.0000x reference)
#include <cuda_runtime.h>
#include <math.h>

#define NROWS 16384
#define KC    2048
#define DD    512
#define EPSF  1e-8f

// output layout (float32, concatenated tuple)
#define Q_OFF    0
#define LOSS_OFF 8388608
#define IDX_OFF  41943040
#define CBV_OFF  41959424
#define CNT_OFF  43008000

// ---- scratch (device globals; no allocations allowed) ----
__device__ float  g_sim[(size_t)NROWS * KC];   // 134 MB similarity matrix
__device__ float  g_rowmax[NROWS];
__device__ float  g_rowinvZ[NROWS];
__device__ int    g_argmax[NROWS];
__device__ float  g_counts[KC];
__device__ float  g_div[KC];
__device__ double g_ent;
__device__ float  g_loss;

// ---- packed f32x2 helpers (Blackwell FFMA2) ----
__device__ __forceinline__ unsigned long long pk2(float x, float y) {
    unsigned long long r;
    asm("mov.b64 %0, {%1,%2};" : "=l"(r) : "f"(x), "f"(y));
    return r;
}
__device__ __forceinline__ void fma2(unsigned long long& c, unsigned long long a, unsigned long long b) {
    asm("fma.rn.f32x2 %0, %1, %2, %0;" : "+l"(c) : "l"(a), "l"(b));
}
__device__ __forceinline__ float2 upk2(unsigned long long c) {
    float2 f;
    asm("mov.b64 {%0,%1}, %2;" : "=f"(f.x), "=f"(f.y) : "l"(c));
    return f;
}

// ---------------------------------------------------------------------------
// 0) zero accumulators (must run every launch — graph replays)
// ---------------------------------------------------------------------------
__global__ void zero_kernel() {
    int gid = blockIdx.x * blockDim.x + threadIdx.x;  // 2048 threads
    g_div[gid] = 0.f;
    g_counts[gid] = 0.f;
    if (gid == 0) g_ent = 0.0;
}

// ---------------------------------------------------------------------------
// 1) fp32 GEMM: S[n,k] = dot(A[n,:], B[k,:]), A=[16384,512], B=[2048,512]
//    128x128 tile, BK=8, 256 threads, 8x8 microtile via packed fma.rn.f32x2
// ---------------------------------------------------------------------------
__global__ __launch_bounds__(256, 2) void gemm_kernel(const float* __restrict__ A,
                                                      const float* __restrict__ B) {
    __shared__ float As[8][132];
    __shared__ float Bs[8][132];
    const int tid = threadIdx.x;
    const int kb = blockIdx.x;     // 0..15
    const int nb = blockIdx.y;     // 0..127
    const int n0 = nb * 128, k0 = kb * 128;
    const int ty = tid >> 4, tx = tid & 15;
    const int lrow = tid >> 1;
    const int lcol = (tid & 1) * 4;
    const float* Ap = A + (size_t)(n0 + lrow) * DD + lcol;
    const float* Bp = B + (size_t)(k0 + lrow) * DD + lcol;

    unsigned long long acc[8][4];
#pragma unroll
    for (int i = 0; i < 8; i++)
#pragma unroll
        for (int j = 0; j < 4; j++) acc[i][j] = 0ULL;

    float4 av = *(const float4*)(Ap);
    float4 bv = *(const float4*)(Bp);

    for (int d0 = 0; d0 < DD; d0 += 8) {
        As[lcol + 0][lrow] = av.x; As[lcol + 1][lrow] = av.y;
        As[lcol + 2][lrow] = av.z; As[lcol + 3][lrow] = av.w;
        Bs[lcol + 0][lrow] = bv.x; Bs[lcol + 1][lrow] = bv.y;
        Bs[lcol + 2][lrow] = bv.z; Bs[lcol + 3][lrow] = bv.w;
        __syncthreads();
        if (d0 + 8 < DD) {  // prefetch next chunk
            av = *(const float4*)(Ap + d0 + 8);
            bv = *(const float4*)(Bp + d0 + 8);
        }
#pragma unroll
        for (int d = 0; d < 8; d++) {
            float4 a0 = *(const float4*)&As[d][ty * 8];
            float4 a1 = *(const float4*)&As[d][ty * 8 + 4];
            const unsigned long long* bp = (const unsigned long long*)&Bs[d][tx * 8];
            unsigned long long b0 = bp[0], b1 = bp[1], b2 = bp[2], b3 = bp[3];
            float aa[8] = {a0.x, a0.y, a0.z, a0.w, a1.x, a1.y, a1.z, a1.w};
#pragma unroll
            for (int i = 0; i < 8; i++) {
                unsigned long long pa = pk2(aa[i], aa[i]);
                fma2(acc[i][0], pa, b0);
                fma2(acc[i][1], pa, b1);
                fma2(acc[i][2], pa, b2);
                fma2(acc[i][3], pa, b3);
            }
        }
        __syncthreads();
    }

#pragma unroll
    for (int i = 0; i < 8; i++) {
        float* Crow = g_sim + (size_t)(n0 + ty * 8 + i) * KC + k0 + tx * 8;
        float2 c0 = upk2(acc[i][0]), c1 = upk2(acc[i][1]);
        float2 c2 = upk2(acc[i][2]), c3 = upk2(acc[i][3]);
        *(float4*)Crow       = make_float4(c0.x, c0.y, c1.x, c1.y);
        *(float4*)(Crow + 4) = make_float4(c2.x, c2.y, c3.x, c3.y);
    }
}

// ---------------------------------------------------------------------------
// 2) per-row: max, argmax (first-index tie-break), sum(exp), counts
// ---------------------------------------------------------------------------
__global__ __launch_bounds__(256) void rowstats_kernel() {
    const int n = blockIdx.x;
    const int t = threadIdx.x;
    const float* row = g_sim + (size_t)n * KC;
    float4 v0 = *(const float4*)(row + t * 8);
    float4 v1 = *(const float4*)(row + t * 8 + 4);
    float s[8] = {v0.x, v0.y, v0.z, v0.w, v1.x, v1.y, v1.z, v1.w};

    float m = s[0]; int mi = t * 8;
#pragma unroll
    for (int j = 1; j < 8; j++)
        if (s[j] > m) { m = s[j]; mi = t * 8 + j; }

    __shared__ float sm[256];
    __shared__ int   si[256];
    sm[t] = m; si[t] = mi;
    __syncthreads();
    for (int off = 128; off > 0; off >>= 1) {
        if (t < off) {
            float o = sm[t + off]; int oi = si[t + off];
            if (o > sm[t] || (o == sm[t] && oi < si[t])) { sm[t] = o; si[t] = oi; }
        }
        __syncthreads();
    }
    const float M = sm[0];
    const int amax = si[0];

    float sum = 0.f;
#pragma unroll
    for (int j = 0; j < 8; j++) sum += __expf(s[j] - M);
    __syncthreads();
    sm[t] = sum;
    __syncthreads();
    for (int off = 128; off > 0; off >>= 1) {
        if (t < off) sm[t] += sm[t + off];
        __syncthreads();
    }
    if (t == 0) {
        g_rowmax[n]  = M;
        g_rowinvZ[n] = 1.0f / sm[0];
        g_argmax[n]  = amax;
        atomicAdd(&g_counts[amax], 1.0f);
    }
}

// ---------------------------------------------------------------------------
// 3) entropy sum + diversity column sums (coalesced tile pass over g_sim)
//    grid: (16 k-chunks of 128, 64 row-chunks of 256), 256 threads
// ---------------------------------------------------------------------------
__global__ __launch_bounds__(256) void entdiv_kernel() {
    const int t = threadIdx.x;
    const int k = blockIdx.x * 128 + (t & 127);
    const int half = t >> 7;
    const int n0 = blockIdx.y * 256;

    __shared__ float shM[256], shZ[256];
    shM[t] = g_rowmax[n0 + t];
    shZ[t] = g_rowinvZ[n0 + t];
    __syncthreads();

    float dacc = 0.f, eacc = 0.f;
#pragma unroll 4
    for (int i = 0; i < 128; i++) {
        int nr = i * 2 + half;
        float s = g_sim[(size_t)(n0 + nr) * KC + k];
        float p = __expf(s - shM[nr]) * shZ[nr];
        dacc += p;
        eacc += p * __log2f(p + EPSF);
    }

    __shared__ float red[256];
    red[t] = dacc;
    __syncthreads();
    if (half == 0) atomicAdd(&g_div[k], red[t] + red[t + 128]);
    __syncthreads();
    red[t] = eacc;
    __syncthreads();
    for (int off = 128; off > 0; off >>= 1) {
        if (t < off) red[t] += red[t + off];
        __syncthreads();
    }
    if (t == 0) atomicAdd(&g_ent, (double)red[0]);
}

// ---------------------------------------------------------------------------
// 4) finalize scalar loss
// ---------------------------------------------------------------------------
__global__ __launch_bounds__(256) void finalize_kernel() {
    const int t = threadIdx.x;
    double acc = 0.0;
    for (int kk = t; kk < KC; kk += 256) {
        float dv = g_div[kk] * (1.0f / (float)NROWS);
        acc += (double)(dv * __log2f(dv + EPSF));
    }
    __shared__ double red[256];
    red[t] = acc;
    __syncthreads();
    for (int off = 128; off > 0; off >>= 1) {
        if (t < off) red[t] += red[t + off];
        __syncthreads();
    }
    if (t == 0) {
        double h_div = -red[0];
        double h_clust = -g_ent / (double)NROWS;
        g_loss = (float)(h_clust - 1.0 * h_div);
    }
}

// ---------------------------------------------------------------------------
// 5) quantized: gather codebook[argmax], center, l2-normalize, STE combine
// ---------------------------------------------------------------------------
__global__ __launch_bounds__(128) void quant_kernel(const float* __restrict__ inputs,
                                                    const float* __restrict__ codebook,
                                                    float* __restrict__ out) {
    const int n = blockIdx.x;
    const int t = threadIdx.x;
    const int idx = g_argmax[n];
    float4 c = *(const float4*)(codebook + (size_t)idx * DD + t * 4);

    __shared__ float red[128];
    red[t] = c.x + c.y + c.z + c.w;
    __syncthreads();
    for (int off = 64; off > 0; off >>= 1) {
        if (t < off) red[t] += red[t + off];
        __syncthreads();
    }
    const float mean = red[0] * (1.0f / (float)DD);
    __syncthreads();
    c.x -= mean; c.y -= mean; c.z -= mean; c.w -= mean;
    red[t] = c.x * c.x + c.y * c.y + c.z * c.z + c.w * c.w;
    __syncthreads();
    for (int off = 64; off > 0; off >>= 1) {
        if (t < off) red[t] += red[t + off];
        __syncthreads();
    }
    const float inv = 1.0f / sqrtf(red[0]);

    float4 in = *(const float4*)(inputs + (size_t)n * DD + t * 4);
    float4 o;
    o.x = in.x + (c.x * inv - in.x);
    o.y = in.y + (c.y * inv - in.y);
    o.z = in.z + (c.z * inv - in.z);
    o.w = in.w + (c.w * inv - in.w);
    *(float4*)(out + Q_OFF + (size_t)n * DD + t * 4) = o;
}

// ---------------------------------------------------------------------------
// 6) broadcast scalar loss into 33.5M elements
// ---------------------------------------------------------------------------
__global__ void fill_loss_kernel(float* __restrict__ out_loss) {
    const float L = g_loss;
    float4 v = make_float4(L, L, L, L);
    float4* o = (float4*)out_loss;
    size_t i = (size_t)blockIdx.x * blockDim.x + threadIdx.x;
    size_t stride = (size_t)gridDim.x * blockDim.x;
    for (; i < (size_t)(33554432 / 4); i += stride) o[i] = v;
}

// ---------------------------------------------------------------------------
// 7) misc outputs: nn_idx (as float), codebook copy, new_counts
// ---------------------------------------------------------------------------
__global__ void misc_kernel(const float* __restrict__ codebook,
                            const float* __restrict__ cc,
                            const int* __restrict__ train,
                            float* __restrict__ out) {
    int gid = blockIdx.x * blockDim.x + threadIdx.x;  // 1048576 threads
    out[CBV_OFF + gid] = codebook[gid];
    if (gid < NROWS) out[IDX_OFF + gid] = (float)g_argmax[gid];
    if (gid < KC) {
        float c = cc[gid];
        out[CNT_OFF + gid] = (*train) ? (0.99f * c + 0.01f * g_counts[gid]) : c;
    }
}

// ---------------------------------------------------------------------------
extern "C" void kernel_launch(void* const* d_in, const int* in_sizes, int n_in,
                              void* d_out, int out_size) {
    const float* inputs   = (const float*)d_in[0];  // [32,512,512]
    const float* codebook = (const float*)d_in[1];  // [2048,512]
    const float* cc       = (const float*)d_in[2];  // [2048]
    const int*   train    = (const int*)d_in[3];    // scalar
    float* out = (float*)d_out;

    zero_kernel<<<8, 256>>>();
    dim3 gg(16, 128);
    gemm_kernel<<<gg, 256>>>(inputs, codebook);
    rowstats_kernel<<<NROWS, 256>>>();
    dim3 ge(16, 64);
    entdiv_kernel<<<ge, 256>>>();
    finalize_kernel<<<1, 256>>>();
    quant_kernel<<<NROWS, 128>>>(inputs, codebook, out);
    fill_loss_kernel<<<2048, 256>>>(out + LOSS_OFF);
    misc_kernel<<<4096, 256>>>(codebook, cc, train, out);
}

// round 7
// speedup vs baseline: 1.6931x; 1.6931x over previous
#include <cuda_runtime.h>
#include <cuda_bf16.h>
#include <math.h>
#include <stdint.h>

#define NROWS 16384
#define KC    2048
#define DD    512
#define EPSF  1e-8f

// output layout (float32, concatenated tuple)
#define Q_OFF    0
#define LOSS_OFF 8388608
#define IDX_OFF  41943040
#define CBV_OFF  41959424
#define CNT_OFF  43008000

// ---- scratch (device globals; no allocations allowed) ----
__device__ float  g_sim[(size_t)NROWS * KC];   // 134 MB similarity matrix
__device__ float  g_rowmax[NROWS];
__device__ float  g_rowinvZ[NROWS];
__device__ int    g_cand1[NROWS];
__device__ int    g_cand2[NROWS];
__device__ int    g_argmax[NROWS];
__device__ float  g_counts[KC];
__device__ float  g_div[KC];
__device__ double g_ent;
__device__ float  g_loss;

// ============================================================================
// helpers
// ============================================================================
__device__ __forceinline__ uint32_t smem_to_u32(const void* p) {
    uint32_t a;
    asm("{ .reg .u64 t; cvta.to.shared.u64 t, %1; cvt.u32.u64 %0, t; }"
        : "=r"(a) : "l"(p));
    return a;
}
__device__ __forceinline__ void cpa16(uint32_t saddr, const void* g) {
    asm volatile("cp.async.cg.shared.global [%0], [%1], 16;" :: "r"(saddr), "l"(g) : "memory");
}
__device__ __forceinline__ uint32_t f2tf32(float x) {
    uint32_t r;
    asm("cvt.rna.tf32.f32 %0, %1;" : "=r"(r) : "f"(x));
    return r;
}
__device__ __forceinline__ void mma_tf32(float* c, const uint32_t* a, const uint32_t* b) {
    asm volatile(
        "mma.sync.aligned.m16n8k8.row.col.f32.tf32.tf32.f32 "
        "{%0,%1,%2,%3}, {%4,%5,%6,%7}, {%8,%9}, {%0,%1,%2,%3};"
        : "+f"(c[0]), "+f"(c[1]), "+f"(c[2]), "+f"(c[3])
        : "r"(a[0]), "r"(a[1]), "r"(a[2]), "r"(a[3]), "r"(b[0]), "r"(b[1]));
}

// ---------------------------------------------------------------------------
// 0) zero accumulators (must run every launch — graph replays)
// ---------------------------------------------------------------------------
__global__ void zero_kernel() {
    int gid = blockIdx.x * blockDim.x + threadIdx.x;  // 2048 threads
    g_div[gid] = 0.f;
    g_counts[gid] = 0.f;
    if (gid == 0) g_ent = 0.0;
}

// ---------------------------------------------------------------------------
// 1) TF32 mma.sync GEMM: S[n,k] = dot(A[n,:], B[k,:])
//    tile 256(M tokens) x 128(N centroids), BK=16, 3-stage cp.async pipeline
//    8 warps (4x2), warp tile 64x64, m16n8k8
// ---------------------------------------------------------------------------
#define TM 256
#define TN 128
#define BK 16
#define PAD_STRIDE 20                              // floats per smem row
#define A_STAGE_FLOATS (TM * PAD_STRIDE)           // 5120
#define B_STAGE_FLOATS (TN * PAD_STRIDE)           // 2560
#define STAGE_FLOATS   (A_STAGE_FLOATS + B_STAGE_FLOATS)   // 7680
#define GEMM_SMEM_BYTES (3 * STAGE_FLOATS * 4)     // 92160

__device__ __forceinline__ void gemm_load_stage(uint32_t sb, int stage, int d0,
                                                const float* __restrict__ A,
                                                const float* __restrict__ B,
                                                int n0, int k0, int tid) {
    uint32_t base = sb + (uint32_t)((stage % 3) * STAGE_FLOATS * 4);
#pragma unroll
    for (int i = 0; i < 4; i++) {                  // A: 256 rows x 16 floats
        int idx = tid + i * 256;                   // 0..1023
        int row = idx >> 2, c = idx & 3;
        cpa16(base + (uint32_t)(row * PAD_STRIDE + c * 4) * 4,
              A + (size_t)(n0 + row) * DD + d0 + c * 4);
    }
#pragma unroll
    for (int i = 0; i < 2; i++) {                  // B: 128 rows x 16 floats
        int idx = tid + i * 256;                   // 0..511
        int row = idx >> 2, c = idx & 3;
        cpa16(base + (uint32_t)(A_STAGE_FLOATS + row * PAD_STRIDE + c * 4) * 4,
              B + (size_t)(k0 + row) * DD + d0 + c * 4);
    }
    asm volatile("cp.async.commit_group;" ::: "memory");
}

__global__ __launch_bounds__(256, 1) void gemm_tf32_kernel(const float* __restrict__ A,
                                                           const float* __restrict__ B) {
    extern __shared__ float smf[];
    const uint32_t sb = smem_to_u32(smf);
    const int tid = threadIdx.x;
    const int warp = tid >> 5;
    const int lane = tid & 31;
    const int wm = warp >> 1;      // 0..3
    const int wn = warp & 1;       // 0..1
    const int n0 = blockIdx.y * TM;
    const int k0 = blockIdx.x * TN;
    const int lr = lane >> 2;      // 0..7
    const int lc = lane & 3;       // 0..3

    float acc[4][8][4];
#pragma unroll
    for (int mi = 0; mi < 4; mi++)
#pragma unroll
        for (int ni = 0; ni < 8; ni++)
#pragma unroll
            for (int j = 0; j < 4; j++) acc[mi][ni][j] = 0.f;

    gemm_load_stage(sb, 0, 0, A, B, n0, k0, tid);
    gemm_load_stage(sb, 1, BK, A, B, n0, k0, tid);

    const int NSTAGE = DD / BK;    // 32
    for (int s = 0; s < NSTAGE; s++) {
        if (s + 2 < NSTAGE) {
            gemm_load_stage(sb, s + 2, (s + 2) * BK, A, B, n0, k0, tid);
            asm volatile("cp.async.wait_group 2;" ::: "memory");
        } else if (s + 1 < NSTAGE) {
            asm volatile("cp.async.wait_group 1;" ::: "memory");
        } else {
            asm volatile("cp.async.wait_group 0;" ::: "memory");
        }
        __syncthreads();

        const float* As = smf + (s % 3) * STAGE_FLOATS + wm * 64 * PAD_STRIDE;
        const float* Bs = smf + (s % 3) * STAGE_FLOATS + A_STAGE_FLOATS + wn * 64 * PAD_STRIDE;

#pragma unroll
        for (int kk = 0; kk < BK; kk += 8) {
            uint32_t af[4][4], bf[8][2];
#pragma unroll
            for (int mi = 0; mi < 4; mi++) {
                const float* ap = As + (mi * 16 + lr) * PAD_STRIDE + kk + lc;
                af[mi][0] = f2tf32(ap[0]);
                af[mi][1] = f2tf32(ap[8 * PAD_STRIDE]);
                af[mi][2] = f2tf32(ap[4]);
                af[mi][3] = f2tf32(ap[8 * PAD_STRIDE + 4]);
            }
#pragma unroll
            for (int ni = 0; ni < 8; ni++) {
                const float* bp = Bs + (ni * 8 + lr) * PAD_STRIDE + kk + lc;
                bf[ni][0] = f2tf32(bp[0]);
                bf[ni][1] = f2tf32(bp[4]);
            }
#pragma unroll
            for (int mi = 0; mi < 4; mi++)
#pragma unroll
                for (int ni = 0; ni < 8; ni++)
                    mma_tf32(acc[mi][ni], af[mi], bf[ni]);
        }
        __syncthreads();
    }

    // epilogue: write 64x64 per warp
#pragma unroll
    for (int mi = 0; mi < 4; mi++) {
        const int m = n0 + wm * 64 + mi * 16 + lr;
#pragma unroll
        for (int ni = 0; ni < 8; ni++) {
            const int c = k0 + wn * 64 + ni * 8 + lc * 2;
            *(float2*)(g_sim + (size_t)m * KC + c) =
                make_float2(acc[mi][ni][0], acc[mi][ni][1]);
            *(float2*)(g_sim + (size_t)(m + 8) * KC + c) =
                make_float2(acc[mi][ni][2], acc[mi][ni][3]);
        }
    }
}

// ---------------------------------------------------------------------------
// 2) per-row: top-2 candidates (ordered-key packing), max, sum(exp)
// ---------------------------------------------------------------------------
__device__ __forceinline__ unsigned long long mk_key(float v, int idx) {
    uint32_t u = __float_as_uint(v);
    u = (u & 0x80000000u) ? ~u : (u | 0x80000000u);
    return ((unsigned long long)u << 32) | (uint32_t)(~(uint32_t)idx);
}
__device__ __forceinline__ int key_idx(unsigned long long k) {
    return (int)(~(uint32_t)k);
}
__device__ __forceinline__ float key_val(unsigned long long k) {
    uint32_t u = (uint32_t)(k >> 32);
    uint32_t ob = (u & 0x80000000u) ? (u ^ 0x80000000u) : ~u;
    return __uint_as_float(ob);
}

__global__ __launch_bounds__(256) void rowstats_kernel() {
    const int n = blockIdx.x;
    const int t = threadIdx.x;
    const float* row = g_sim + (size_t)n * KC;
    float4 v0 = *(const float4*)(row + t * 8);
    float4 v1 = *(const float4*)(row + t * 8 + 4);
    float s[8] = {v0.x, v0.y, v0.z, v0.w, v1.x, v1.y, v1.z, v1.w};

    unsigned long long k1 = 0, k2 = 0;
#pragma unroll
    for (int j = 0; j < 8; j++) {
        unsigned long long u = mk_key(s[j], t * 8 + j);
        if (u > k1) { k2 = k1; k1 = u; }
        else if (u > k2) k2 = u;
    }

    __shared__ unsigned long long K1[256], K2[256];
    K1[t] = k1; K2[t] = k2;
    __syncthreads();
    for (int off = 128; off > 0; off >>= 1) {
        if (t < off) {
            unsigned long long a1 = K1[t], a2 = K2[t];
            unsigned long long b1 = K1[t + off], b2 = K2[t + off];
            unsigned long long r1 = (a1 > b1) ? a1 : b1;
            unsigned long long r2 = (a1 > b1) ? ((a2 > b1) ? a2 : b1)
                                              : ((b2 > a1) ? b2 : a1);
            K1[t] = r1; K2[t] = r2;
        }
        __syncthreads();
    }
    const float M = key_val(K1[0]);

    float sum = 0.f;
#pragma unroll
    for (int j = 0; j < 8; j++) sum += __expf(s[j] - M);
    __shared__ float red[256];
    red[t] = sum;
    __syncthreads();
    for (int off = 128; off > 0; off >>= 1) {
        if (t < off) red[t] += red[t + off];
        __syncthreads();
    }
    if (t == 0) {
        g_rowmax[n]  = M;
        g_rowinvZ[n] = 1.0f / red[0];
        g_cand1[n]   = key_idx(K1[0]);
        g_cand2[n]   = key_idx(K2[0]);
    }
}

// ---------------------------------------------------------------------------
// 2b) exact argmax fixup: fp64 dots for the two candidates, pick the winner
// ---------------------------------------------------------------------------
__global__ __launch_bounds__(128) void argfix_kernel(const float* __restrict__ A,
                                                     const float* __restrict__ cb) {
    const int n = blockIdx.x;
    const int t = threadIdx.x;
    const int i1 = g_cand1[n], i2 = g_cand2[n];
    const float* ar = A + (size_t)n * DD;
    const float* c1 = cb + (size_t)i1 * DD;
    const float* c2 = cb + (size_t)i2 * DD;
    double a1 = 0.0, a2 = 0.0;
#pragma unroll
    for (int j = t; j < DD; j += 128) {
        double x = (double)ar[j];
        a1 += x * (double)c1[j];
        a2 += x * (double)c2[j];
    }
    __shared__ double r1[128], r2[128];
    r1[t] = a1; r2[t] = a2;
    __syncthreads();
    for (int off = 64; off > 0; off >>= 1) {
        if (t < off) { r1[t] += r1[t + off]; r2[t] += r2[t + off]; }
        __syncthreads();
    }
    if (t == 0) {
        int pick = i1;
        if (r2[0] > r1[0] || (r2[0] == r1[0] && i2 < i1)) pick = i2;
        g_argmax[n] = pick;
        atomicAdd(&g_counts[pick], 1.0f);
    }
}

// ---------------------------------------------------------------------------
// 3) entropy sum + diversity column sums (coalesced tile pass over g_sim)
// ---------------------------------------------------------------------------
__global__ __launch_bounds__(256) void entdiv_kernel() {
    const int t = threadIdx.x;
    const int k = blockIdx.x * 128 + (t & 127);
    const int half = t >> 7;
    const int n0 = blockIdx.y * 256;

    __shared__ float shM[256], shZ[256];
    shM[t] = g_rowmax[n0 + t];
    shZ[t] = g_rowinvZ[n0 + t];
    __syncthreads();

    float dacc = 0.f, eacc = 0.f;
#pragma unroll 4
    for (int i = 0; i < 128; i++) {
        int nr = i * 2 + half;
        float s = g_sim[(size_t)(n0 + nr) * KC + k];
        float p = __expf(s - shM[nr]) * shZ[nr];
        dacc += p;
        eacc += p * __log2f(p + EPSF);
    }

    __shared__ float red[256];
    red[t] = dacc;
    __syncthreads();
    if (half == 0) atomicAdd(&g_div[k], red[t] + red[t + 128]);
    __syncthreads();
    red[t] = eacc;
    __syncthreads();
    for (int off = 128; off > 0; off >>= 1) {
        if (t < off) red[t] += red[t + off];
        __syncthreads();
    }
    if (t == 0) atomicAdd(&g_ent, (double)red[0]);
}

// ---------------------------------------------------------------------------
// 4) finalize scalar loss
// ---------------------------------------------------------------------------
__global__ __launch_bounds__(256) void finalize_kernel() {
    const int t = threadIdx.x;
    double acc = 0.0;
    for (int kk = t; kk < KC; kk += 256) {
        float dv = g_div[kk] * (1.0f / (float)NROWS);
        acc += (double)(dv * __log2f(dv + EPSF));
    }
    __shared__ double red[256];
    red[t] = acc;
    __syncthreads();
    for (int off = 128; off > 0; off >>= 1) {
        if (t < off) red[t] += red[t + off];
        __syncthreads();
    }
    if (t == 0) {
        double h_div = -red[0];
        double h_clust = -g_ent / (double)NROWS;
        g_loss = (float)(h_clust - 1.0 * h_div);
    }
}

// ---------------------------------------------------------------------------
// 5) quantized: gather codebook[argmax], center, l2-normalize, STE combine
// ---------------------------------------------------------------------------
__global__ __launch_bounds__(128) void quant_kernel(const float* __restrict__ inputs,
                                                    const float* __restrict__ codebook,
                                                    float* __restrict__ out) {
    const int n = blockIdx.x;
    const int t = threadIdx.x;
    const int idx = g_argmax[n];
    float4 c = *(const float4*)(codebook + (size_t)idx * DD + t * 4);

    __shared__ float red[128];
    red[t] = c.x + c.y + c.z + c.w;
    __syncthreads();
    for (int off = 64; off > 0; off >>= 1) {
        if (t < off) red[t] += red[t + off];
        __syncthreads();
    }
    const float mean = red[0] * (1.0f / (float)DD);
    __syncthreads();
    c.x -= mean; c.y -= mean; c.z -= mean; c.w -= mean;
    red[t] = c.x * c.x + c.y * c.y + c.z * c.z + c.w * c.w;
    __syncthreads();
    for (int off = 64; off > 0; off >>= 1) {
        if (t < off) red[t] += red[t + off];
        __syncthreads();
    }
    const float inv = 1.0f / sqrtf(red[0]);

    float4 in = *(const float4*)(inputs + (size_t)n * DD + t * 4);
    float4 o;
    o.x = in.x + (c.x * inv - in.x);
    o.y = in.y + (c.y * inv - in.y);
    o.z = in.z + (c.z * inv - in.z);
    o.w = in.w + (c.w * inv - in.w);
    *(float4*)(out + Q_OFF + (size_t)n * DD + t * 4) = o;
}

// ---------------------------------------------------------------------------
// 6) broadcast scalar loss into 33.5M elements
// ---------------------------------------------------------------------------
__global__ void fill_loss_kernel(float* __restrict__ out_loss) {
    const float L = g_loss;
    float4 v = make_float4(L, L, L, L);
    float4* o = (float4*)out_loss;
    size_t i = (size_t)blockIdx.x * blockDim.x + threadIdx.x;
    size_t stride = (size_t)gridDim.x * blockDim.x;
    for (; i < (size_t)(33554432 / 4); i += stride) o[i] = v;
}

// ---------------------------------------------------------------------------
// 7) misc outputs: nn_idx (as float), codebook copy, new_counts
// ---------------------------------------------------------------------------
__global__ void misc_kernel(const float* __restrict__ codebook,
                            const float* __restrict__ cc,
                            const int* __restrict__ train,
                            float* __restrict__ out) {
    int gid = blockIdx.x * blockDim.x + threadIdx.x;  // 1048576 threads
    out[CBV_OFF + gid] = codebook[gid];
    if (gid < NROWS) out[IDX_OFF + gid] = (float)g_argmax[gid];
    if (gid < KC) {
        float c = cc[gid];
        out[CNT_OFF + gid] = (*train) ? (0.99f * c + 0.01f * g_counts[gid]) : c;
    }
}

// ---------------------------------------------------------------------------
extern "C" void kernel_launch(void* const* d_in, const int* in_sizes, int n_in,
                              void* d_out, int out_size) {
    const float* inputs   = (const float*)d_in[0];  // [32,512,512]
    const float* codebook = (const float*)d_in[1];  // [2048,512]
    const float* cc       = (const float*)d_in[2];  // [2048]
    const int*   train    = (const int*)d_in[3];    // scalar
    float* out = (float*)d_out;

    cudaFuncSetAttribute(gemm_tf32_kernel,
                         cudaFuncAttributeMaxDynamicSharedMemorySize, GEMM_SMEM_BYTES);

    zero_kernel<<<8, 256>>>();
    dim3 gg(KC / TN, NROWS / TM);   // (16, 64)
    gemm_tf32_kernel<<<gg, 256, GEMM_SMEM_BYTES>>>(inputs, codebook);
    rowstats_kernel<<<NROWS, 256>>>();
    argfix_kernel<<<NROWS, 128>>>(inputs, codebook);
    dim3 ge(16, 64);
    entdiv_kernel<<<ge, 256>>>();
    finalize_kernel<<<1, 256>>>();
    quant_kernel<<<NROWS, 128>>>(inputs, codebook, out);
    fill_loss_kernel<<<2048, 256>>>(out + LOSS_OFF);
    misc_kernel<<<4096, 256>>>(codebook, cc, train, out);
}

// round 8
// speedup vs baseline: 2.4111x; 1.4241x over previous
#include <cuda_runtime.h>
#include <cuda_fp16.h>
#include <math.h>
#include <stdint.h>

#define NROWS 16384
#define KC    2048
#define DD    512
#define EPSF  1e-8f

// output layout (float32, concatenated tuple)
#define Q_OFF    0
#define LOSS_OFF 8388608
#define IDX_OFF  41943040
#define CBV_OFF  41959424
#define CNT_OFF  43008000

// ---- scratch (device globals; no allocations allowed) ----
__device__ float  g_sim[(size_t)NROWS * KC];   // 134 MB similarity matrix
__device__ __half g_ah[(size_t)NROWS * DD];
__device__ __half g_bh[(size_t)KC * DD];
__device__ float  g_rowmax[NROWS];
__device__ float  g_rowinvZ[NROWS];
__device__ float  g_hrow[NROWS];
__device__ int    g_cand1[NROWS];
__device__ int    g_cand2[NROWS];
__device__ int    g_argmax[NROWS];
__device__ float  g_counts[KC];
__device__ float  g_div[KC];
__device__ float  g_loss;

// ============================================================================
// helpers
// ============================================================================
__device__ __forceinline__ uint32_t smem_to_u32(const void* p) {
    uint32_t a;
    asm("{ .reg .u64 t; cvta.to.shared.u64 t, %1; cvt.u32.u64 %0, t; }"
        : "=r"(a) : "l"(p));
    return a;
}
__device__ __forceinline__ void cpa16(uint32_t saddr, const void* g) {
    asm volatile("cp.async.cg.shared.global [%0], [%1], 16;" :: "r"(saddr), "l"(g) : "memory");
}
__device__ __forceinline__ void mma_f16(float* c, const uint32_t* a, const uint32_t* b) {
    asm volatile(
        "mma.sync.aligned.m16n8k16.row.col.f32.f16.f16.f32 "
        "{%0,%1,%2,%3}, {%4,%5,%6,%7}, {%8,%9}, {%0,%1,%2,%3};"
        : "+f"(c[0]), "+f"(c[1]), "+f"(c[2]), "+f"(c[3])
        : "r"(a[0]), "r"(a[1]), "r"(a[2]), "r"(a[3]), "r"(b[0]), "r"(b[1]));
}

// ---------------------------------------------------------------------------
// 0) zero accumulators (must run every launch — graph replays)
// ---------------------------------------------------------------------------
__global__ void zero_kernel() {
    int gid = blockIdx.x * blockDim.x + threadIdx.x;  // 2048 threads
    g_div[gid] = 0.f;
    g_counts[gid] = 0.f;
}

// ---------------------------------------------------------------------------
// 0b) convert inputs/codebook fp32 -> fp16
// ---------------------------------------------------------------------------
__global__ __launch_bounds__(256) void convert_kernel(const float* __restrict__ A,
                                                      const float* __restrict__ B) {
    const int NA8 = (NROWS * DD) / 8;   // 1048576
    int gid = blockIdx.x * blockDim.x + threadIdx.x;  // up to 1179648
    const float* src;
    __half* dst;
    if (gid < NA8) {
        src = A + (size_t)gid * 8;
        dst = g_ah + (size_t)gid * 8;
    } else {
        int g2 = gid - NA8;
        src = B + (size_t)g2 * 8;
        dst = g_bh + (size_t)g2 * 8;
    }
    float4 v0 = *(const float4*)(src);
    float4 v1 = *(const float4*)(src + 4);
    __half2 h0 = __floats2half2_rn(v0.x, v0.y);
    __half2 h1 = __floats2half2_rn(v0.z, v0.w);
    __half2 h2 = __floats2half2_rn(v1.x, v1.y);
    __half2 h3 = __floats2half2_rn(v1.z, v1.w);
    uint4 o;
    o.x = *(uint32_t*)&h0; o.y = *(uint32_t*)&h1;
    o.z = *(uint32_t*)&h2; o.w = *(uint32_t*)&h3;
    *(uint4*)dst = o;
}

// ---------------------------------------------------------------------------
// 1) fp16 mma.sync GEMM: S[n,k] = dot(A[n,:], B[k,:]), fp32 accum
//    tile 256(M) x 128(N), BK=32 halves, 4-stage cp.async pipeline
//    8 warps (4x2), warp tile 64x64, m16n8k16
// ---------------------------------------------------------------------------
#define TM 256
#define TN 128
#define BKH 32
#define PADH 40                                    // halves per padded smem row
#define A_ST_H (TM * PADH)                         // 10240
#define B_ST_H (TN * PADH)                         // 5120
#define ST_H   (A_ST_H + B_ST_H)                   // 15360 halves = 30720 B
#define GEMM_SMEM_BYTES (4 * ST_H * 2)             // 122880

__device__ __forceinline__ void gemm_load_stage(uint32_t sb, int stage, int d0,
                                                int n0, int k0, int tid) {
    uint32_t base = sb + (uint32_t)((stage & 3) * ST_H * 2);
#pragma unroll
    for (int i = 0; i < 4; i++) {                  // A: 256 rows x 32 halves
        int idx = tid + i * 256;                   // 0..1023
        int row = idx >> 2, c = idx & 3;
        cpa16(base + (uint32_t)(row * PADH + c * 8) * 2,
              g_ah + (size_t)(n0 + row) * DD + d0 + c * 8);
    }
#pragma unroll
    for (int i = 0; i < 2; i++) {                  // B: 128 rows x 32 halves
        int idx = tid + i * 256;                   // 0..511
        int row = idx >> 2, c = idx & 3;
        cpa16(base + (uint32_t)(A_ST_H + row * PADH + c * 8) * 2,
              g_bh + (size_t)(k0 + row) * DD + d0 + c * 8);
    }
    asm volatile("cp.async.commit_group;" ::: "memory");
}

__global__ __launch_bounds__(256, 1) void gemm_f16_kernel() {
    extern __shared__ __half smh[];
    const uint32_t sb = smem_to_u32(smh);
    const int tid = threadIdx.x;
    const int warp = tid >> 5;
    const int lane = tid & 31;
    const int wm = warp >> 1;      // 0..3
    const int wn = warp & 1;       // 0..1
    const int n0 = blockIdx.y * TM;
    const int k0 = blockIdx.x * TN;
    const int lr = lane >> 2;      // 0..7
    const int lc = lane & 3;       // 0..3

    float acc[4][8][4];
#pragma unroll
    for (int mi = 0; mi < 4; mi++)
#pragma unroll
        for (int ni = 0; ni < 8; ni++)
#pragma unroll
            for (int j = 0; j < 4; j++) acc[mi][ni][j] = 0.f;

    gemm_load_stage(sb, 0, 0, n0, k0, tid);
    gemm_load_stage(sb, 1, BKH, n0, k0, tid);
    gemm_load_stage(sb, 2, 2 * BKH, n0, k0, tid);

    const int NST = DD / BKH;      // 16
    for (int s = 0; s < NST; s++) {
        if (s + 3 < NST) {
            gemm_load_stage(sb, s + 3, (s + 3) * BKH, n0, k0, tid);
            asm volatile("cp.async.wait_group 3;" ::: "memory");
        } else if (s + 2 < NST) {
            asm volatile("cp.async.wait_group 2;" ::: "memory");
        } else if (s + 1 < NST) {
            asm volatile("cp.async.wait_group 1;" ::: "memory");
        } else {
            asm volatile("cp.async.wait_group 0;" ::: "memory");
        }
        __syncthreads();

        const __half* As = smh + (s & 3) * ST_H + wm * 64 * PADH;
        const __half* Bs = smh + (s & 3) * ST_H + A_ST_H + wn * 64 * PADH;

#pragma unroll
        for (int kk = 0; kk < BKH; kk += 16) {
            uint32_t af[4][4], bf[8][2];
#pragma unroll
            for (int mi = 0; mi < 4; mi++) {
                const __half* ap = As + (mi * 16 + lr) * PADH + kk + lc * 2;
                af[mi][0] = *(const uint32_t*)(ap);
                af[mi][1] = *(const uint32_t*)(ap + 8 * PADH);
                af[mi][2] = *(const uint32_t*)(ap + 8);
                af[mi][3] = *(const uint32_t*)(ap + 8 * PADH + 8);
            }
#pragma unroll
            for (int ni = 0; ni < 8; ni++) {
                const __half* bp = Bs + (ni * 8 + lr) * PADH + kk + lc * 2;
                bf[ni][0] = *(const uint32_t*)(bp);
                bf[ni][1] = *(const uint32_t*)(bp + 8);
            }
#pragma unroll
            for (int mi = 0; mi < 4; mi++)
#pragma unroll
                for (int ni = 0; ni < 8; ni++)
                    mma_f16(acc[mi][ni], af[mi], bf[ni]);
        }
        __syncthreads();
    }

    // epilogue: write 64x64 per warp
#pragma unroll
    for (int mi = 0; mi < 4; mi++) {
        const int m = n0 + wm * 64 + mi * 16 + lr;
#pragma unroll
        for (int ni = 0; ni < 8; ni++) {
            const int c = k0 + wn * 64 + ni * 8 + lc * 2;
            *(float2*)(g_sim + (size_t)m * KC + c) =
                make_float2(acc[mi][ni][0], acc[mi][ni][1]);
            *(float2*)(g_sim + (size_t)(m + 8) * KC + c) =
                make_float2(acc[mi][ni][2], acc[mi][ni][3]);
        }
    }
}

// ---------------------------------------------------------------------------
// 2) per-row: top-2 candidates, max, sum(exp), per-row entropy (fused)
// ---------------------------------------------------------------------------
__device__ __forceinline__ unsigned long long mk_key(float v, int idx) {
    uint32_t u = __float_as_uint(v);
    u = (u & 0x80000000u) ? ~u : (u | 0x80000000u);
    return ((unsigned long long)u << 32) | (uint32_t)(~(uint32_t)idx);
}
__device__ __forceinline__ int key_idx(unsigned long long k) {
    return (int)(~(uint32_t)k);
}
__device__ __forceinline__ float key_val(unsigned long long k) {
    uint32_t u = (uint32_t)(k >> 32);
    uint32_t ob = (u & 0x80000000u) ? (u ^ 0x80000000u) : ~u;
    return __uint_as_float(ob);
}

__global__ __launch_bounds__(256) void rowstats_kernel() {
    const int n = blockIdx.x;
    const int t = threadIdx.x;
    const float* row = g_sim + (size_t)n * KC;
    float4 v0 = *(const float4*)(row + t * 8);
    float4 v1 = *(const float4*)(row + t * 8 + 4);
    float s[8] = {v0.x, v0.y, v0.z, v0.w, v1.x, v1.y, v1.z, v1.w};

    unsigned long long k1 = 0, k2 = 0;
#pragma unroll
    for (int j = 0; j < 8; j++) {
        unsigned long long u = mk_key(s[j], t * 8 + j);
        if (u > k1) { k2 = k1; k1 = u; }
        else if (u > k2) k2 = u;
    }

    __shared__ unsigned long long K1[256], K2[256];
    K1[t] = k1; K2[t] = k2;
    __syncthreads();
    for (int off = 128; off > 0; off >>= 1) {
        if (t < off) {
            unsigned long long a1 = K1[t], a2 = K2[t];
            unsigned long long b1 = K1[t + off], b2 = K2[t + off];
            unsigned long long r1 = (a1 > b1) ? a1 : b1;
            unsigned long long r2 = (a1 > b1) ? ((a2 > b1) ? a2 : b1)
                                              : ((b2 > a1) ? b2 : a1);
            K1[t] = r1; K2[t] = r2;
        }
        __syncthreads();
    }
    const float M = key_val(K1[0]);

    float e[8];
    float sum = 0.f;
#pragma unroll
    for (int j = 0; j < 8; j++) { e[j] = __expf(s[j] - M); sum += e[j]; }
    __shared__ float red[256];
    red[t] = sum;
    __syncthreads();
    for (int off = 128; off > 0; off >>= 1) {
        if (t < off) red[t] += red[t + off];
        __syncthreads();
    }
    const float invZ = 1.0f / red[0];

    // per-row entropy term: sum_k q * log2(q + eps)
    float eacc = 0.f;
#pragma unroll
    for (int j = 0; j < 8; j++) {
        float q = e[j] * invZ;
        eacc += q * __log2f(q + EPSF);
    }
    __syncthreads();
    red[t] = eacc;
    __syncthreads();
    for (int off = 128; off > 0; off >>= 1) {
        if (t < off) red[t] += red[t + off];
        __syncthreads();
    }
    if (t == 0) {
        g_rowmax[n]  = M;
        g_rowinvZ[n] = invZ;
        g_hrow[n]    = red[0];
        g_cand1[n]   = key_idx(K1[0]);
        g_cand2[n]   = key_idx(K2[0]);
    }
}

// ---------------------------------------------------------------------------
// 2b) exact argmax fixup: compensated fp32 dots (TwoProd+split err), fp64
//     only in the final block reduction
// ---------------------------------------------------------------------------
__global__ __launch_bounds__(128) void argfix_kernel(const float* __restrict__ A,
                                                     const float* __restrict__ cb) {
    const int n = blockIdx.x;
    const int t = threadIdx.x;
    const int i1 = g_cand1[n], i2 = g_cand2[n];
    const float* ar = A + (size_t)n * DD;
    const float* c1 = cb + (size_t)i1 * DD;
    const float* c2 = cb + (size_t)i2 * DD;
    float s1 = 0.f, e1 = 0.f, s2 = 0.f, e2 = 0.f;
#pragma unroll
    for (int j = t; j < DD; j += 128) {
        float x = ar[j];
        float y1 = c1[j], y2 = c2[j];
        float p1 = x * y1;
        e1 += __fmaf_rn(x, y1, -p1);
        s1 += p1;
        float p2 = x * y2;
        e2 += __fmaf_rn(x, y2, -p2);
        s2 += p2;
    }
    __shared__ double r1[128], r2[128];
    r1[t] = (double)s1 + (double)e1;
    r2[t] = (double)s2 + (double)e2;
    __syncthreads();
    for (int off = 64; off > 0; off >>= 1) {
        if (t < off) { r1[t] += r1[t + off]; r2[t] += r2[t + off]; }
        __syncthreads();
    }
    if (t == 0) {
        int pick = i1;
        if (r2[0] > r1[0] || (r2[0] == r1[0] && i2 < i1)) pick = i2;
        g_argmax[n] = pick;
        atomicAdd(&g_counts[pick], 1.0f);
    }
}

// ---------------------------------------------------------------------------
// 3) diversity column sums (coalesced tile pass over g_sim)
// ---------------------------------------------------------------------------
__global__ __launch_bounds__(256) void entdiv_kernel() {
    const int t = threadIdx.x;
    const int k = blockIdx.x * 128 + (t & 127);
    const int half = t >> 7;
    const int n0 = blockIdx.y * 256;

    __shared__ float shM[256], shZ[256];
    shM[t] = g_rowmax[n0 + t];
    shZ[t] = g_rowinvZ[n0 + t];
    __syncthreads();

    float dacc = 0.f;
#pragma unroll 4
    for (int i = 0; i < 128; i++) {
        int nr = i * 2 + half;
        float s = g_sim[(size_t)(n0 + nr) * KC + k];
        dacc += __expf(s - shM[nr]) * shZ[nr];
    }

    __shared__ float red[256];
    red[t] = dacc;
    __syncthreads();
    if (half == 0) atomicAdd(&g_div[k], red[t] + red[t + 128]);
}

// ---------------------------------------------------------------------------
// 4) finalize scalar loss: h_clust from g_hrow, h_div from g_div
// ---------------------------------------------------------------------------
__global__ __launch_bounds__(256) void finalize_kernel() {
    const int t = threadIdx.x;
    double acc_h = 0.0;
    for (int i = t; i < NROWS; i += 256) acc_h += (double)g_hrow[i];
    double acc_d = 0.0;
    for (int kk = t; kk < KC; kk += 256) {
        float dv = g_div[kk] * (1.0f / (float)NROWS);
        acc_d += (double)(dv * __log2f(dv + EPSF));
    }
    __shared__ double rh[256], rd[256];
    rh[t] = acc_h; rd[t] = acc_d;
    __syncthreads();
    for (int off = 128; off > 0; off >>= 1) {
        if (t < off) { rh[t] += rh[t + off]; rd[t] += rd[t + off]; }
        __syncthreads();
    }
    if (t == 0) {
        // h_clust = -mean(rowent); h_div = -acc_d; loss = h_clust - h_div
        g_loss = (float)(-rh[0] / (double)NROWS + rd[0]);
    }
}

// ---------------------------------------------------------------------------
// 5) quantized: gather codebook[argmax], center, l2-normalize, STE combine
// ---------------------------------------------------------------------------
__global__ __launch_bounds__(128) void quant_kernel(const float* __restrict__ inputs,
                                                    const float* __restrict__ codebook,
                                                    float* __restrict__ out) {
    const int n = blockIdx.x;
    const int t = threadIdx.x;
    const int idx = g_argmax[n];
    float4 c = *(const float4*)(codebook + (size_t)idx * DD + t * 4);

    __shared__ float red[128];
    red[t] = c.x + c.y + c.z + c.w;
    __syncthreads();
    for (int off = 64; off > 0; off >>= 1) {
        if (t < off) red[t] += red[t + off];
        __syncthreads();
    }
    const float mean = red[0] * (1.0f / (float)DD);
    __syncthreads();
    c.x -= mean; c.y -= mean; c.z -= mean; c.w -= mean;
    red[t] = c.x * c.x + c.y * c.y + c.z * c.z + c.w * c.w;
    __syncthreads();
    for (int off = 64; off > 0; off >>= 1) {
        if (t < off) red[t] += red[t + off];
        __syncthreads();
    }
    const float inv = 1.0f / sqrtf(red[0]);

    float4 in = *(const float4*)(inputs + (size_t)n * DD + t * 4);
    float4 o;
    o.x = in.x + (c.x * inv - in.x);
    o.y = in.y + (c.y * inv - in.y);
    o.z = in.z + (c.z * inv - in.z);
    o.w = in.w + (c.w * inv - in.w);
    *(float4*)(out + Q_OFF + (size_t)n * DD + t * 4) = o;
}

// ---------------------------------------------------------------------------
// 6) broadcast scalar loss into 33.5M elements
// ---------------------------------------------------------------------------
__global__ void fill_loss_kernel(float* __restrict__ out_loss) {
    const float L = g_loss;
    float4 v = make_float4(L, L, L, L);
    float4* o = (float4*)out_loss;
    size_t i = (size_t)blockIdx.x * blockDim.x + threadIdx.x;
    size_t stride = (size_t)gridDim.x * blockDim.x;
    for (; i < (size_t)(33554432 / 4); i += stride) o[i] = v;
}

// ---------------------------------------------------------------------------
// 7) misc outputs: nn_idx (as float), codebook copy, new_counts
// ---------------------------------------------------------------------------
__global__ void misc_kernel(const float* __restrict__ codebook,
                            const float* __restrict__ cc,
                            const int* __restrict__ train,
                            float* __restrict__ out) {
    int gid = blockIdx.x * blockDim.x + threadIdx.x;  // 1048576 threads
    out[CBV_OFF + gid] = codebook[gid];
    if (gid < NROWS) out[IDX_OFF + gid] = (float)g_argmax[gid];
    if (gid < KC) {
        float c = cc[gid];
        out[CNT_OFF + gid] = (*train) ? (0.99f * c + 0.01f * g_counts[gid]) : c;
    }
}

// ---------------------------------------------------------------------------
extern "C" void kernel_launch(void* const* d_in, const int* in_sizes, int n_in,
                              void* d_out, int out_size) {
    const float* inputs   = (const float*)d_in[0];  // [32,512,512]
    const float* codebook = (const float*)d_in[1];  // [2048,512]
    const float* cc       = (const float*)d_in[2];  // [2048]
    const int*   train    = (const int*)d_in[3];    // scalar
    float* out = (float*)d_out;

    cudaFuncSetAttribute(gemm_f16_kernel,
                         cudaFuncAttributeMaxDynamicSharedMemorySize, GEMM_SMEM_BYTES);

    zero_kernel<<<8, 256>>>();
    convert_kernel<<<4608, 256>>>(inputs, codebook);
    dim3 gg(KC / TN, NROWS / TM);   // (16, 64)
    gemm_f16_kernel<<<gg, 256, GEMM_SMEM_BYTES>>>();
    rowstats_kernel<<<NROWS, 256>>>();
    argfix_kernel<<<NROWS, 128>>>(inputs, codebook);
    dim3 ge(16, 64);
    entdiv_kernel<<<ge, 256>>>();
    finalize_kernel<<<1, 256>>>();
    quant_kernel<<<NROWS, 128>>>(inputs, codebook, out);
    fill_loss_kernel<<<2048, 256>>>(out + LOSS_OFF);
    misc_kernel<<<4096, 256>>>(codebook, cc, train, out);
}

// round 9
// speedup vs baseline: 2.4801x; 1.0286x over previous
#include <cuda_runtime.h>
#include <cuda_fp16.h>
#include <math.h>
#include <stdint.h>

#define NROWS 16384
#define KC    2048
#define DD    512
#define EPSF  1e-8f

// output layout (float32, concatenated tuple)
#define Q_OFF    0
#define LOSS_OFF 8388608
#define IDX_OFF  41943040
#define CBV_OFF  41959424
#define CNT_OFF  43008000

// ---- scratch (device globals; no allocations allowed) ----
__device__ float  g_sim[(size_t)NROWS * KC];   // 134 MB similarity matrix
__device__ __half g_ah[(size_t)NROWS * DD];
__device__ __half g_bh[(size_t)KC * DD];
__device__ float4 g_pA[(size_t)NROWS * 16];    // per (row, ktile): max, i1, second, i2
__device__ float  g_pZ[(size_t)NROWS * 16];    // per (row, ktile): sumexp rel tile max
__device__ float  g_rowmax[NROWS];
__device__ float  g_rowinvZ[NROWS];
__device__ int    g_cand1[NROWS];
__device__ int    g_cand2[NROWS];
__device__ int    g_argmax[NROWS];
__device__ float  g_counts[KC];
__device__ float  g_div[KC];
__device__ double g_ent;
__device__ float  g_loss;

// ============================================================================
// helpers
// ============================================================================
__device__ __forceinline__ uint32_t smem_to_u32(const void* p) {
    uint32_t a;
    asm("{ .reg .u64 t; cvta.to.shared.u64 t, %1; cvt.u32.u64 %0, t; }"
        : "=r"(a) : "l"(p));
    return a;
}
__device__ __forceinline__ void cpa16(uint32_t saddr, const void* g) {
    asm volatile("cp.async.cg.shared.global [%0], [%1], 16;" :: "r"(saddr), "l"(g) : "memory");
}
__device__ __forceinline__ void mma_f16(float* c, const uint32_t* a, const uint32_t* b) {
    asm volatile(
        "mma.sync.aligned.m16n8k16.row.col.f32.f16.f16.f32 "
        "{%0,%1,%2,%3}, {%4,%5,%6,%7}, {%8,%9}, {%0,%1,%2,%3};"
        : "+f"(c[0]), "+f"(c[1]), "+f"(c[2]), "+f"(c[3])
        : "r"(a[0]), "r"(a[1]), "r"(a[2]), "r"(a[3]), "r"(b[0]), "r"(b[1]));
}

// ---------------------------------------------------------------------------
// 0) zero accumulators (must run every launch — graph replays)
// ---------------------------------------------------------------------------
__global__ void zero_kernel() {
    int gid = blockIdx.x * blockDim.x + threadIdx.x;  // 2048 threads
    g_div[gid] = 0.f;
    g_counts[gid] = 0.f;
    if (gid == 0) g_ent = 0.0;
}

// ---------------------------------------------------------------------------
// 0b) convert inputs/codebook fp32 -> fp16
// ---------------------------------------------------------------------------
__global__ __launch_bounds__(256) void convert_kernel(const float* __restrict__ A,
                                                      const float* __restrict__ B) {
    const int NA8 = (NROWS * DD) / 8;   // 1048576
    int gid = blockIdx.x * blockDim.x + threadIdx.x;  // up to 1179648
    const float* src;
    __half* dst;
    if (gid < NA8) {
        src = A + (size_t)gid * 8;
        dst = g_ah + (size_t)gid * 8;
    } else {
        int g2 = gid - NA8;
        src = B + (size_t)g2 * 8;
        dst = g_bh + (size_t)g2 * 8;
    }
    float4 v0 = *(const float4*)(src);
    float4 v1 = *(const float4*)(src + 4);
    __half2 h0 = __floats2half2_rn(v0.x, v0.y);
    __half2 h1 = __floats2half2_rn(v0.z, v0.w);
    __half2 h2 = __floats2half2_rn(v1.x, v1.y);
    __half2 h3 = __floats2half2_rn(v1.z, v1.w);
    uint4 o;
    o.x = *(uint32_t*)&h0; o.y = *(uint32_t*)&h1;
    o.z = *(uint32_t*)&h2; o.w = *(uint32_t*)&h3;
    *(uint4*)dst = o;
}

// ---------------------------------------------------------------------------
// 1) fp16 mma.sync GEMM + fused per-tile row statistics in epilogue
//    tile 256(M) x 128(N), BK=32 halves, 4-stage cp.async pipeline
// ---------------------------------------------------------------------------
#define TM 256
#define TN 128
#define BKH 32
#define PADH 40                                    // halves per padded smem row
#define A_ST_H (TM * PADH)                         // 10240
#define B_ST_H (TN * PADH)                         // 5120
#define ST_H   (A_ST_H + B_ST_H)                   // 15360 halves = 30720 B
#define GEMM_SMEM_BYTES (4 * ST_H * 2)             // 122880

__device__ __forceinline__ void gemm_load_stage(uint32_t sb, int stage, int d0,
                                                int n0, int k0, int tid) {
    uint32_t base = sb + (uint32_t)((stage & 3) * ST_H * 2);
#pragma unroll
    for (int i = 0; i < 4; i++) {                  // A: 256 rows x 32 halves
        int idx = tid + i * 256;                   // 0..1023
        int row = idx >> 2, c = idx & 3;
        cpa16(base + (uint32_t)(row * PADH + c * 8) * 2,
              g_ah + (size_t)(n0 + row) * DD + d0 + c * 8);
    }
#pragma unroll
    for (int i = 0; i < 2; i++) {                  // B: 128 rows x 32 halves
        int idx = tid + i * 256;                   // 0..511
        int row = idx >> 2, c = idx & 3;
        cpa16(base + (uint32_t)(A_ST_H + row * PADH + c * 8) * 2,
              g_bh + (size_t)(k0 + row) * DD + d0 + c * 8);
    }
    asm volatile("cp.async.commit_group;" ::: "memory");
}

__global__ __launch_bounds__(256, 1) void gemm_f16_kernel() {
    extern __shared__ __half smh[];
    const uint32_t sb = smem_to_u32(smh);
    const int tid = threadIdx.x;
    const int warp = tid >> 5;
    const int lane = tid & 31;
    const int wm = warp >> 1;      // 0..3
    const int wn = warp & 1;       // 0..1
    const int n0 = blockIdx.y * TM;
    const int k0 = blockIdx.x * TN;
    const int lr = lane >> 2;      // 0..7
    const int lc = lane & 3;       // 0..3

    float acc[4][8][4];
#pragma unroll
    for (int mi = 0; mi < 4; mi++)
#pragma unroll
        for (int ni = 0; ni < 8; ni++)
#pragma unroll
            for (int j = 0; j < 4; j++) acc[mi][ni][j] = 0.f;

    gemm_load_stage(sb, 0, 0, n0, k0, tid);
    gemm_load_stage(sb, 1, BKH, n0, k0, tid);
    gemm_load_stage(sb, 2, 2 * BKH, n0, k0, tid);

    const int NST = DD / BKH;      // 16
    for (int s = 0; s < NST; s++) {
        if (s + 3 < NST) {
            gemm_load_stage(sb, s + 3, (s + 3) * BKH, n0, k0, tid);
            asm volatile("cp.async.wait_group 3;" ::: "memory");
        } else if (s + 2 < NST) {
            asm volatile("cp.async.wait_group 2;" ::: "memory");
        } else if (s + 1 < NST) {
            asm volatile("cp.async.wait_group 1;" ::: "memory");
        } else {
            asm volatile("cp.async.wait_group 0;" ::: "memory");
        }
        __syncthreads();

        const __half* As = smh + (s & 3) * ST_H + wm * 64 * PADH;
        const __half* Bs = smh + (s & 3) * ST_H + A_ST_H + wn * 64 * PADH;

#pragma unroll
        for (int kk = 0; kk < BKH; kk += 16) {
            uint32_t af[4][4], bf[8][2];
#pragma unroll
            for (int mi = 0; mi < 4; mi++) {
                const __half* ap = As + (mi * 16 + lr) * PADH + kk + lc * 2;
                af[mi][0] = *(const uint32_t*)(ap);
                af[mi][1] = *(const uint32_t*)(ap + 8 * PADH);
                af[mi][2] = *(const uint32_t*)(ap + 8);
                af[mi][3] = *(const uint32_t*)(ap + 8 * PADH + 8);
            }
#pragma unroll
            for (int ni = 0; ni < 8; ni++) {
                const __half* bp = Bs + (ni * 8 + lr) * PADH + kk + lc * 2;
                bf[ni][0] = *(const uint32_t*)(bp);
                bf[ni][1] = *(const uint32_t*)(bp + 8);
            }
#pragma unroll
            for (int mi = 0; mi < 4; mi++)
#pragma unroll
                for (int ni = 0; ni < 8; ni++)
                    mma_f16(acc[mi][ni], af[mi], bf[ni]);
        }
        __syncthreads();
    }

    // ---- epilogue A: write sim block (fp32) ----
#pragma unroll
    for (int mi = 0; mi < 4; mi++) {
        const int m = n0 + wm * 64 + mi * 16 + lr;
#pragma unroll
        for (int ni = 0; ni < 8; ni++) {
            const int c = k0 + wn * 64 + ni * 8 + lc * 2;
            *(float2*)(g_sim + (size_t)m * KC + c) =
                make_float2(acc[mi][ni][0], acc[mi][ni][1]);
            *(float2*)(g_sim + (size_t)(m + 8) * KC + c) =
                make_float2(acc[mi][ni][2], acc[mi][ni][3]);
        }
    }

    // ---- epilogue B: per-row tile stats (max/i1/second/i2/sumexp) ----
    // smem reuse: partA float4[256][2] (8KB) + partZ float[256][2] (2KB)
    float4* partA = (float4*)smh;
    float*  partZ = (float*)(partA + 512);

#pragma unroll
    for (int mi = 0; mi < 4; mi++) {
#pragma unroll
        for (int h = 0; h < 2; h++) {
            const int rrow = wm * 64 + mi * 16 + lr + 8 * h;
            float v1 = -1e30f, v2 = -1e30f;
            int i1 = 0x7fffffff, i2 = 0x7fffffff;
            float vals[16];
#pragma unroll
            for (int ni = 0; ni < 8; ni++) {
#pragma unroll
                for (int q = 0; q < 2; q++) {
                    float v = acc[mi][ni][h * 2 + q];
                    int col = k0 + wn * 64 + ni * 8 + lc * 2 + q;
                    vals[ni * 2 + q] = v;
                    if (v > v1 || (v == v1 && col < i1)) {
                        v2 = v1; i2 = i1; v1 = v; i1 = col;
                    } else if (v > v2 || (v == v2 && col < i2)) {
                        v2 = v; i2 = col;
                    }
                }
            }
            // merge top-2 across the 4 lanes sharing this row (xor 1,2, width 4)
#pragma unroll
            for (int off = 1; off < 4; off <<= 1) {
                float ov1 = __shfl_xor_sync(0xffffffffu, v1, off, 4);
                int   oi1 = __shfl_xor_sync(0xffffffffu, i1, off, 4);
                float ov2 = __shfl_xor_sync(0xffffffffu, v2, off, 4);
                int   oi2 = __shfl_xor_sync(0xffffffffu, i2, off, 4);
                if (ov1 > v1 || (ov1 == v1 && oi1 < i1)) {
                    float nv2; int ni2;
                    if (v1 > ov2 || (v1 == ov2 && i1 < oi2)) { nv2 = v1; ni2 = i1; }
                    else { nv2 = ov2; ni2 = oi2; }
                    v1 = ov1; i1 = oi1; v2 = nv2; i2 = ni2;
                } else if (ov1 > v2 || (ov1 == v2 && oi1 < i2)) {
                    v2 = ov1; i2 = oi1;
                }
            }
            // sumexp relative to the (warp-half) max v1
            float se = 0.f;
#pragma unroll
            for (int j = 0; j < 16; j++) se += __expf(vals[j] - v1);
            se += __shfl_xor_sync(0xffffffffu, se, 1, 4);
            se += __shfl_xor_sync(0xffffffffu, se, 2, 4);
            if (lc == 0) {
                partA[rrow * 2 + wn] = make_float4(v1, __int_as_float(i1),
                                                   v2, __int_as_float(i2));
                partZ[rrow * 2 + wn] = se;
            }
        }
    }
    __syncthreads();

    // combine the two 64-col halves -> one partial per (row, ktile)
    if (tid < 256) {
        float4 a = partA[tid * 2], b = partA[tid * 2 + 1];
        float za = partZ[tid * 2], zb = partZ[tid * 2 + 1];
        int ia1 = __float_as_int(a.y), ia2 = __float_as_int(a.w);
        int ib1 = __float_as_int(b.y), ib2 = __float_as_int(b.w);
        float M, S; int I1, I2;
        if (a.x > b.x || (a.x == b.x && ia1 < ib1)) {
            M = a.x; I1 = ia1;
            if (b.x > a.z || (b.x == a.z && ib1 < ia2)) { S = b.x; I2 = ib1; }
            else { S = a.z; I2 = ia2; }
        } else {
            M = b.x; I1 = ib1;
            if (a.x > b.z || (a.x == b.z && ia1 < ib2)) { S = a.x; I2 = ia1; }
            else { S = b.z; I2 = ib2; }
        }
        float Z = za * __expf(a.x - M) + zb * __expf(b.x - M);
        g_pA[(size_t)(n0 + tid) * 16 + blockIdx.x] =
            make_float4(M, __int_as_float(I1), S, __int_as_float(I2));
        g_pZ[(size_t)(n0 + tid) * 16 + blockIdx.x] = Z;
    }
}

// ---------------------------------------------------------------------------
// 2) combine 16 tile-partials per row -> global max, invZ, cand1, cand2
//    (16 lanes per row; 2 rows per warp)
// ---------------------------------------------------------------------------
__global__ __launch_bounds__(256) void combine_kernel() {
    const int tid = threadIdx.x;
    const int warp = tid >> 5;
    const int lane = tid & 31;
    const int n = blockIdx.x * 16 + warp * 2 + (lane >> 4);
    const int e = lane & 15;

    float4 a = g_pA[(size_t)n * 16 + e];
    float z  = g_pZ[(size_t)n * 16 + e];
    const float tM = a.x;
    const int   tI = __float_as_int(a.y);
    const float tS = a.z;
    const int   tI2 = __float_as_int(a.w);

    float M = tM; int I = tI;
#pragma unroll
    for (int off = 8; off; off >>= 1) {
        float oM = __shfl_xor_sync(0xffffffffu, M, off, 16);
        int   oI = __shfl_xor_sync(0xffffffffu, I, off, 16);
        if (oM > M || (oM == M && oI < I)) { M = oM; I = oI; }
    }
    float zz = z * __expf(tM - M);
#pragma unroll
    for (int off = 8; off; off >>= 1)
        zz += __shfl_xor_sync(0xffffffffu, zz, off, 16);

    float c; int ci;
    if (tI != I) { c = tM; ci = tI; } else { c = tS; ci = tI2; }
#pragma unroll
    for (int off = 8; off; off >>= 1) {
        float oc = __shfl_xor_sync(0xffffffffu, c, off, 16);
        int  oci = __shfl_xor_sync(0xffffffffu, ci, off, 16);
        if (oc > c || (oc == c && oci < ci)) { c = oc; ci = oci; }
    }
    if (e == 0) {
        g_rowmax[n]  = M;
        g_rowinvZ[n] = 1.0f / zz;
        g_cand1[n]   = I;
        g_cand2[n]   = ci;
    }
}

// ---------------------------------------------------------------------------
// 2b) exact argmax fixup: compensated fp32 dots, fp64 only in final combine
// ---------------------------------------------------------------------------
__global__ __launch_bounds__(128) void argfix_kernel(const float* __restrict__ A,
                                                     const float* __restrict__ cb) {
    const int n = blockIdx.x;
    const int t = threadIdx.x;
    const int i1 = g_cand1[n], i2 = g_cand2[n];
    const float* ar = A + (size_t)n * DD;
    const float* c1 = cb + (size_t)i1 * DD;
    const float* c2 = cb + (size_t)i2 * DD;
    float s1 = 0.f, e1 = 0.f, s2 = 0.f, e2 = 0.f;
#pragma unroll
    for (int j = t; j < DD; j += 128) {
        float x = ar[j];
        float y1 = c1[j], y2 = c2[j];
        float p1 = x * y1;
        e1 += __fmaf_rn(x, y1, -p1);
        s1 += p1;
        float p2 = x * y2;
        e2 += __fmaf_rn(x, y2, -p2);
        s2 += p2;
    }
    __shared__ double r1[128], r2[128];
    r1[t] = (double)s1 + (double)e1;
    r2[t] = (double)s2 + (double)e2;
    __syncthreads();
    for (int off = 64; off > 0; off >>= 1) {
        if (t < off) { r1[t] += r1[t + off]; r2[t] += r2[t + off]; }
        __syncthreads();
    }
    if (t == 0) {
        int pick = i1;
        if (r2[0] > r1[0] || (r2[0] == r1[0] && i2 < i1)) pick = i2;
        g_argmax[n] = pick;
        atomicAdd(&g_counts[pick], 1.0f);
    }
}

// ---------------------------------------------------------------------------
// 3) entropy sum + diversity column sums (single coalesced pass over g_sim)
// ---------------------------------------------------------------------------
__global__ __launch_bounds__(256) void entdiv_kernel() {
    const int t = threadIdx.x;
    const int k = blockIdx.x * 128 + (t & 127);
    const int half = t >> 7;
    const int n0 = blockIdx.y * 256;

    __shared__ float shM[256], shZ[256];
    shM[t] = g_rowmax[n0 + t];
    shZ[t] = g_rowinvZ[n0 + t];
    __syncthreads();

    float dacc = 0.f, eacc = 0.f;
#pragma unroll 4
    for (int i = 0; i < 128; i++) {
        int nr = i * 2 + half;
        float s = __ldcs(&g_sim[(size_t)(n0 + nr) * KC + k]);
        float p = __expf(s - shM[nr]) * shZ[nr];
        dacc += p;
        eacc += p * __log2f(p + EPSF);
    }

    __shared__ float red[256];
    red[t] = dacc;
    __syncthreads();
    if (half == 0) atomicAdd(&g_div[k], red[t] + red[t + 128]);
    __syncthreads();
    red[t] = eacc;
    __syncthreads();
    for (int off = 128; off > 0; off >>= 1) {
        if (t < off) red[t] += red[t + off];
        __syncthreads();
    }
    if (t == 0) atomicAdd(&g_ent, (double)red[0]);
}

// ---------------------------------------------------------------------------
// 4) finalize scalar loss
// ---------------------------------------------------------------------------
__global__ __launch_bounds__(256) void finalize_kernel() {
    const int t = threadIdx.x;
    double acc = 0.0;
    for (int kk = t; kk < KC; kk += 256) {
        float dv = g_div[kk] * (1.0f / (float)NROWS);
        acc += (double)(dv * __log2f(dv + EPSF));
    }
    __shared__ double red[256];
    red[t] = acc;
    __syncthreads();
    for (int off = 128; off > 0; off >>= 1) {
        if (t < off) red[t] += red[t + off];
        __syncthreads();
    }
    if (t == 0) {
        double h_div = -red[0];
        double h_clust = -g_ent / (double)NROWS;
        g_loss = (float)(h_clust - 1.0 * h_div);
    }
}

// ---------------------------------------------------------------------------
// 5) quantized: gather codebook[argmax], center, l2-normalize, STE combine
// ---------------------------------------------------------------------------
__global__ __launch_bounds__(128) void quant_kernel(const float* __restrict__ inputs,
                                                    const float* __restrict__ codebook,
                                                    float* __restrict__ out) {
    const int n = blockIdx.x;
    const int t = threadIdx.x;
    const int idx = g_argmax[n];
    float4 c = *(const float4*)(codebook + (size_t)idx * DD + t * 4);

    __shared__ float red[128];
    red[t] = c.x + c.y + c.z + c.w;
    __syncthreads();
    for (int off = 64; off > 0; off >>= 1) {
        if (t < off) red[t] += red[t + off];
        __syncthreads();
    }
    const float mean = red[0] * (1.0f / (float)DD);
    __syncthreads();
    c.x -= mean; c.y -= mean; c.z -= mean; c.w -= mean;
    red[t] = c.x * c.x + c.y * c.y + c.z * c.z + c.w * c.w;
    __syncthreads();
    for (int off = 64; off > 0; off >>= 1) {
        if (t < off) red[t] += red[t + off];
        __syncthreads();
    }
    const float inv = 1.0f / sqrtf(red[0]);

    float4 in = *(const float4*)(inputs + (size_t)n * DD + t * 4);
    float4 o;
    o.x = in.x + (c.x * inv - in.x);
    o.y = in.y + (c.y * inv - in.y);
    o.z = in.z + (c.z * inv - in.z);
    o.w = in.w + (c.w * inv - in.w);
    *(float4*)(out + Q_OFF + (size_t)n * DD + t * 4) = o;
}

// ---------------------------------------------------------------------------
// 6) broadcast scalar loss into 33.5M elements (streaming stores)
// ---------------------------------------------------------------------------
__global__ void fill_loss_kernel(float* __restrict__ out_loss) {
    const float L = g_loss;
    float4 v = make_float4(L, L, L, L);
    float4* o = (float4*)out_loss;
    size_t i = (size_t)blockIdx.x * blockDim.x + threadIdx.x;
    size_t stride = (size_t)gridDim.x * blockDim.x;
    for (; i < (size_t)(33554432 / 4); i += stride) __stcs(&o[i], v);
}

// ---------------------------------------------------------------------------
// 7) misc outputs: nn_idx (as float), codebook copy, new_counts
// ---------------------------------------------------------------------------
__global__ void misc_kernel(const float* __restrict__ codebook,
                            const float* __restrict__ cc,
                            const int* __restrict__ train,
                            float* __restrict__ out) {
    int gid = blockIdx.x * blockDim.x + threadIdx.x;  // 1048576 threads
    out[CBV_OFF + gid] = codebook[gid];
    if (gid < NROWS) out[IDX_OFF + gid] = (float)g_argmax[gid];
    if (gid < KC) {
        float c = cc[gid];
        out[CNT_OFF + gid] = (*train) ? (0.99f * c + 0.01f * g_counts[gid]) : c;
    }
}

// ---------------------------------------------------------------------------
extern "C" void kernel_launch(void* const* d_in, const int* in_sizes, int n_in,
                              void* d_out, int out_size) {
    const float* inputs   = (const float*)d_in[0];  // [32,512,512]
    const float* codebook = (const float*)d_in[1];  // [2048,512]
    const float* cc       = (const float*)d_in[2];  // [2048]
    const int*   train    = (const int*)d_in[3];    // scalar
    float* out = (float*)d_out;

    cudaFuncSetAttribute(gemm_f16_kernel,
                         cudaFuncAttributeMaxDynamicSharedMemorySize, GEMM_SMEM_BYTES);

    zero_kernel<<<8, 256>>>();
    convert_kernel<<<4608, 256>>>(inputs, codebook);
    dim3 gg(KC / TN, NROWS / TM);   // (16, 64)
    gemm_f16_kernel<<<gg, 256, GEMM_SMEM_BYTES>>>();
    combine_kernel<<<NROWS / 16, 256>>>();
    argfix_kernel<<<NROWS, 128>>>(inputs, codebook);
    dim3 ge(16, 64);
    entdiv_kernel<<<ge, 256>>>();
    finalize_kernel<<<1, 256>>>();
    quant_kernel<<<NROWS, 128>>>(inputs, codebook, out);
    fill_loss_kernel<<<2048, 256>>>(out + LOSS_OFF);
    misc_kernel<<<4096, 256>>>(codebook, cc, train, out);
}